// round 10
// baseline (speedup 1.0000x reference)
#include <cuda_runtime.h>
#include <cuda_bf16.h>
#include <math.h>

#define EPS 1e-9f

static constexpr int BMAX = 1024;
static constexpr int DMAX = 512;
static constexpr int UMAX = 512;

// Scratch (device globals — no allocation allowed)
__device__ float2 g_LN [BMAX * DMAX];       // {log2|x+eps|, bitcast(neg ? 0xFFFFFFFF : 0)}
__device__ float4 g_PW4[DMAX * UMAX / 2];   // per u-pair: {p0, w0, p1, w1}
__device__ uint2  g_OM2[DMAX * UMAX / 2];   // per u-pair: odd(p)?0x80000000:0

// ---------------- Fused prepass (also inits out = bias) ----------------
__global__ void prep_kernel(const float* __restrict__ x,
                            const float* __restrict__ w,
                            const float* __restrict__ p,
                            const float* __restrict__ bias,
                            float* __restrict__ out,
                            int nLN, int nPW, int nOut, int U) {
    int i = blockIdx.x * blockDim.x + threadIdx.x;
    if (i < nLN) {
        float xe = x[i] + EPS;
        float2 v;
        v.x = log2f(fabsf(xe));
        v.y = __uint_as_float((xe < 0.f) ? 0xFFFFFFFFu : 0u);
        g_LN[i] = v;
    }
    if (i < nPW) {
        const int U2 = U >> 1;
        int d  = i / U2;
        int u  = (i - d * U2) * 2;
        int idx = d * U + u;
        float p0 = p[idx],     p1 = p[idx + 1];
        float w0 = w[idx],     w1 = w[idx + 1];
        g_PW4[i] = make_float4(p0, w0, p1, w1);
        uint2 m;
        m.x = (fmodf(p0, 2.f) != 0.f) ? 0x80000000u : 0u;
        m.y = (fmodf(p1, 2.f) != 0.f) ? 0x80000000u : 0u;
        g_OM2[i] = m;
    }
    if (i < nOut) out[i] = bias[i % U];
}

// v ^= (om & nm) in ONE LOP3: f(a,b,c) = a ^ (b & c) -> lut 0x78
__device__ __forceinline__ float sign_apply(float v, unsigned om, unsigned nm) {
    unsigned r = __float_as_uint(v);
    asm("lop3.b32 %0, %0, %1, %2, 0x78;" : "+r"(r) : "r"(om), "r"(nm));
    return __uint_as_float(r);
}

// ---------------- Main kernel (compile-time shapes, FULLY UNROLLED) ----------------
// upt=2, TBT=8 b-rows, DSPLIT=16 over D (nD=32 per block, fully unrolled so
// every LDG offset is an immediate: zero addressing ALU in the hot loop).
static constexpr int TBT     = 8;
static constexpr int THREADS = 128;
static constexpr int DSPLIT  = 16;

template <int D, int U>
__global__ __launch_bounds__(THREADS, 8)
void power_layer_kernel(float* __restrict__ out) {
    constexpr int U2 = U / 2;
    constexpr int nD = D / DSPLIT;          // 32

    const int up  = blockIdx.y * THREADS + threadIdx.x;   // u-pair index
    const int b0  = blockIdx.x * TBT;
    const int dlo = blockIdx.z * nD;

    const float4* __restrict__ pwp = g_PW4 + dlo * U2 + up;
    const uint2*  __restrict__ omp = g_OM2 + dlo * U2 + up;
    const float2* __restrict__ lnb = g_LN  + (size_t)b0 * D + dlo;

    float2 acc[TBT];
#pragma unroll
    for (int bb = 0; bb < TBT; bb++) acc[bb] = make_float2(0.f, 0.f);

#pragma unroll
    for (int dd = 0; dd < nD; dd += 2) {
        // All offsets below are compile-time immediates.
        const float4 pw0 = pwp[(dd + 0) * U2];   // {p0,w0,p1,w1} for d=dd
        const float4 pw1 = pwp[(dd + 1) * U2];   //                for d=dd+1
        const uint2  om0 = omp[(dd + 0) * U2];
        const uint2  om1 = omp[(dd + 1) * U2];

#pragma unroll
        for (int bb = 0; bb < TBT; bb++) {
            // warp-uniform broadcast: {log2,negmask} for d=dd and d=dd+1
            const float4 lnv = *(const float4*)(lnb + bb * D + dd);
            const unsigned nm0 = __float_as_uint(lnv.y);
            const unsigned nm1 = __float_as_uint(lnv.w);

            float e00 = pw0.x * lnv.x;
            float e01 = pw0.z * lnv.x;
            float e10 = pw1.x * lnv.z;
            float e11 = pw1.z * lnv.z;
            float v00, v01, v10, v11;
            asm("ex2.approx.f32 %0, %1;" : "=f"(v00) : "f"(e00));
            asm("ex2.approx.f32 %0, %1;" : "=f"(v01) : "f"(e01));
            asm("ex2.approx.f32 %0, %1;" : "=f"(v10) : "f"(e10));
            asm("ex2.approx.f32 %0, %1;" : "=f"(v11) : "f"(e11));
            v00 = sign_apply(v00, om0.x, nm0);
            v01 = sign_apply(v01, om0.y, nm0);
            v10 = sign_apply(v10, om1.x, nm1);
            v11 = sign_apply(v11, om1.y, nm1);
            acc[bb].x = fmaf(pw0.y, v00, acc[bb].x);
            acc[bb].y = fmaf(pw0.w, v01, acc[bb].y);
            acc[bb].x = fmaf(pw1.y, v10, acc[bb].x);
            acc[bb].y = fmaf(pw1.w, v11, acc[bb].y);
        }
    }

    float* o = out + (size_t)b0 * U + 2 * up;
#pragma unroll
    for (int bb = 0; bb < TBT; bb++) {
        atomicAdd(o + bb * U,     acc[bb].x);
        atomicAdd(o + bb * U + 1, acc[bb].y);
    }
}

// ---------------- Generic fallback (only if shapes differ) ----------------
__global__ void fallback_kernel(const float* __restrict__ x,
                                const float* __restrict__ w,
                                const float* __restrict__ p,
                                const float* __restrict__ bias,
                                float* __restrict__ out,
                                int B, int D, int U) {
    int i = blockIdx.x * blockDim.x + threadIdx.x;
    if (i >= B * U) return;
    int b = i / U, u = i % U;
    float s = 0.f;
    for (int d = 0; d < D; d++) {
        float xe = x[b * D + d] + EPS;
        float pv = p[d * U + u];
        float ap = powf(fabsf(xe), pv);
        bool odd = (fmodf(pv, 2.f) != 0.f);
        float sv = (odd && xe < 0.f) ? -ap : ap;
        s += w[d * U + u] * sv;
    }
    out[i] = s + bias[u];
}

// ---------------- Launch ----------------
extern "C" void kernel_launch(void* const* d_in, const int* in_sizes, int n_in,
                              void* d_out, int out_size) {
    const float* x    = (const float*)d_in[0];
    const float* w    = (const float*)d_in[1];
    const float* p    = (const float*)d_in[2];
    const float* bias = (const float*)d_in[3];
    float* out        = (float*)d_out;

    const int U = in_sizes[3];            // 512
    const int D = in_sizes[1] / U;        // 512
    const int B = in_sizes[0] / D;        // 1024

    if (U == 512 && D == 512 && B == 1024) {
        const int nLN  = B * D;           // 524288
        const int nPW  = D * U / 2;       // 131072
        const int nOut = out_size;        // 524288
        int nmax = nLN > nPW ? nLN : nPW;
        if (nOut > nmax) nmax = nOut;
        prep_kernel<<<(nmax + 255) / 256, 256>>>(x, w, p, bias, out,
                                                 nLN, nPW, nOut, U);

        // grid: (B/TBT, U2/THREADS, DSPLIT) = (128, 2, 16) = 4096 blocks
        dim3 grid(B / TBT, (U / 2) / THREADS, DSPLIT);
        power_layer_kernel<512, 512><<<grid, THREADS>>>(out);
    } else {
        int n = B * U;
        fallback_kernel<<<(n + 255) / 256, 256>>>(x, w, p, bias, out, B, D, U);
    }
}

// round 12
// speedup vs baseline: 1.1288x; 1.1288x over previous
#include <cuda_runtime.h>
#include <cuda_bf16.h>
#include <math.h>

#define EPS 1e-9f

static constexpr int BMAX = 1024;
static constexpr int DMAX = 512;
static constexpr int UMAX = 512;

typedef unsigned long long ull;

// Scratch (device globals — no allocation allowed). d-pair-major layouts:
__device__ float4 g_LN4[BMAX * DMAX / 2];        // per (b, d-pair): {l0, l1, nmf0, nmf1}
__device__ float4 g_P4 [DMAX / 2 * UMAX / 2];    // per (d-pair, u-pair): {p(d0,u0), p(d1,u0), p(d0,u1), p(d1,u1)}
__device__ float4 g_W4 [DMAX / 2 * UMAX / 2];    // same layout for w
__device__ float4 g_DW4[DMAX / 2 * UMAX / 2];    // same layout: odd(p) ? -2w : 0

// ---------------- f32x2 helpers (sm_103a packed FP32) ----------------
__device__ __forceinline__ ull pack2(float a, float b) {
    ull r; asm("mov.b64 %0, {%1, %2};" : "=l"(r) : "f"(a), "f"(b)); return r;
}
__device__ __forceinline__ void unpack2(ull p, float& a, float& b) {
    asm("mov.b64 {%0, %1}, %2;" : "=f"(a), "=f"(b) : "l"(p));
}
__device__ __forceinline__ ull mul2(ull a, ull b) {
    ull r; asm("mul.rn.f32x2 %0, %1, %2;" : "=l"(r) : "l"(a), "l"(b)); return r;
}
__device__ __forceinline__ ull fma2(ull a, ull b, ull c) {
    ull r; asm("fma.rn.f32x2 %0, %1, %2, %3;" : "=l"(r) : "l"(a), "l"(b), "l"(c)); return r;
}
__device__ __forceinline__ float ex2(float x) {
    float r; asm("ex2.approx.f32 %0, %1;" : "=f"(r) : "f"(x)); return r;
}

// ---------------- Fused prepass (also inits out = bias) ----------------
__global__ void prep_kernel(const float* __restrict__ x,
                            const float* __restrict__ w,
                            const float* __restrict__ p,
                            const float* __restrict__ bias,
                            float* __restrict__ out,
                            int nLN4, int nPW, int nOut, int D, int U) {
    int i = blockIdx.x * blockDim.x + threadIdx.x;
    const int D2 = D >> 1, U2 = U >> 1;
    if (i < nLN4) {                       // i = b * D2 + dp
        int b  = i / D2;
        int dp = i - b * D2;
        float xe0 = x[b * D + 2 * dp]     + EPS;
        float xe1 = x[b * D + 2 * dp + 1] + EPS;
        float4 v;
        v.x = log2f(fabsf(xe0));
        v.y = log2f(fabsf(xe1));
        v.z = (xe0 < 0.f) ? 1.f : 0.f;
        v.w = (xe1 < 0.f) ? 1.f : 0.f;
        g_LN4[i] = v;
    }
    if (i < nPW) {                        // i = dp * U2 + up
        int dp = i / U2;
        int up = i - dp * U2;
        int base = (2 * dp) * U + 2 * up;
        float p00 = p[base],     p01 = p[base + 1];
        float p10 = p[base + U], p11 = p[base + U + 1];
        float w00 = w[base],     w01 = w[base + 1];
        float w10 = w[base + U], w11 = w[base + U + 1];
        g_P4[i] = make_float4(p00, p10, p01, p11);   // {d0u0, d1u0, d0u1, d1u1}
        g_W4[i] = make_float4(w00, w10, w01, w11);
        float dw00 = (fmodf(p00, 2.f) != 0.f) ? -2.f * w00 : 0.f;
        float dw10 = (fmodf(p10, 2.f) != 0.f) ? -2.f * w10 : 0.f;
        float dw01 = (fmodf(p01, 2.f) != 0.f) ? -2.f * w01 : 0.f;
        float dw11 = (fmodf(p11, 2.f) != 0.f) ? -2.f * w11 : 0.f;
        g_DW4[i] = make_float4(dw00, dw10, dw01, dw11);
    }
    if (i < nOut) out[i] = bias[i % U];
}

// ---------------- Main kernel (compile-time shapes, fully unrolled, f32x2) ----------------
// upt=2, TBT=8 b-rows, DSPLIT=16 over d-pairs (16 d-pairs = 32 d's per block).
// Per 2 elems: MUL2 + 2xMUFU + FMA2(sign) + FMA2(acc) = 5 issue slots.
static constexpr int TBT     = 8;
static constexpr int THREADS = 128;
static constexpr int DSPLIT  = 16;

template <int D, int U>
__global__ __launch_bounds__(THREADS, 7)
void power_layer_kernel(float* __restrict__ out) {
    constexpr int U2  = U / 2;        // 256 u-pairs
    constexpr int D2  = D / 2;        // 256 d-pairs
    constexpr int nDP = D2 / DSPLIT;  // 16 d-pairs per block

    const int up  = blockIdx.y * THREADS + threadIdx.x;   // u-pair index
    const int b0  = blockIdx.x * TBT;
    const int dp0 = blockIdx.z * nDP;

    const float4* __restrict__ Pp  = g_P4  + dp0 * U2 + up;
    const float4* __restrict__ Wp  = g_W4  + dp0 * U2 + up;
    const float4* __restrict__ DWp = g_DW4 + dp0 * U2 + up;
    const float4* __restrict__ LNp = g_LN4 + (size_t)b0 * D2 + dp0;

    ull acc[TBT][2];
#pragma unroll
    for (int bb = 0; bb < TBT; bb++) { acc[bb][0] = 0ull; acc[bb][1] = 0ull; }

#pragma unroll
    for (int j = 0; j < nDP; j++) {
        // Immediate-offset LDG.128s; component pairs are aligned consecutive regs.
        const float4 P  = Pp [j * U2];
        const float4 W  = Wp [j * U2];
        const float4 DW = DWp[j * U2];
        const ull p0  = pack2(P.x,  P.y),  p1  = pack2(P.z,  P.w);
        const ull w0_ = pack2(W.x,  W.y),  w1_ = pack2(W.z,  W.w);
        const ull dw0 = pack2(DW.x, DW.y), dw1 = pack2(DW.z, DW.w);

#pragma unroll
        for (int bb = 0; bb < TBT; bb++) {
            const float4 L  = LNp[bb * D2 + j];     // warp-uniform broadcast
            const ull lp = pack2(L.x, L.y);         // {l0, l1}
            const ull nm = pack2(L.z, L.w);         // {nmf0, nmf1}

            // u0: pair over (d0, d1)
            {
                ull e = mul2(p0, lp);
                float e0, e1; unpack2(e, e0, e1);
                ull v = pack2(ex2(e0), ex2(e1));
                ull ws = fma2(nm, dw0, w0_);        // signed weights
                acc[bb][0] = fma2(ws, v, acc[bb][0]);
            }
            // u1
            {
                ull e = mul2(p1, lp);
                float e0, e1; unpack2(e, e0, e1);
                ull v = pack2(ex2(e0), ex2(e1));
                ull ws = fma2(nm, dw1, w1_);
                acc[bb][1] = fma2(ws, v, acc[bb][1]);
            }
        }
    }

    float* o = out + (size_t)b0 * U + 2 * up;
#pragma unroll
    for (int bb = 0; bb < TBT; bb++) {
        float a0, a1;
        unpack2(acc[bb][0], a0, a1);
        atomicAdd(o + bb * U, a0 + a1);
        unpack2(acc[bb][1], a0, a1);
        atomicAdd(o + bb * U + 1, a0 + a1);
    }
}

// ---------------- Generic fallback (only if shapes differ) ----------------
__global__ void fallback_kernel(const float* __restrict__ x,
                                const float* __restrict__ w,
                                const float* __restrict__ p,
                                const float* __restrict__ bias,
                                float* __restrict__ out,
                                int B, int D, int U) {
    int i = blockIdx.x * blockDim.x + threadIdx.x;
    if (i >= B * U) return;
    int b = i / U, u = i % U;
    float s = 0.f;
    for (int d = 0; d < D; d++) {
        float xe = x[b * D + d] + EPS;
        float pv = p[d * U + u];
        float ap = powf(fabsf(xe), pv);
        bool odd = (fmodf(pv, 2.f) != 0.f);
        float sv = (odd && xe < 0.f) ? -ap : ap;
        s += w[d * U + u] * sv;
    }
    out[i] = s + bias[u];
}

// ---------------- Launch ----------------
extern "C" void kernel_launch(void* const* d_in, const int* in_sizes, int n_in,
                              void* d_out, int out_size) {
    const float* x    = (const float*)d_in[0];
    const float* w    = (const float*)d_in[1];
    const float* p    = (const float*)d_in[2];
    const float* bias = (const float*)d_in[3];
    float* out        = (float*)d_out;

    const int U = in_sizes[3];            // 512
    const int D = in_sizes[1] / U;        // 512
    const int B = in_sizes[0] / D;        // 1024

    if (U == 512 && D == 512 && B == 1024) {
        const int nLN4 = B * D / 2;       // 262144
        const int nPW  = (D / 2) * (U / 2);  // 65536
        const int nOut = out_size;        // 524288
        int nmax = nLN4 > nPW ? nLN4 : nPW;
        if (nOut > nmax) nmax = nOut;
        prep_kernel<<<(nmax + 255) / 256, 256>>>(x, w, p, bias, out,
                                                 nLN4, nPW, nOut, D, U);

        // grid: (B/TBT, U2/THREADS, DSPLIT) = (128, 2, 16) = 4096 blocks
        dim3 grid(B / TBT, (U / 2) / THREADS, DSPLIT);
        power_layer_kernel<512, 512><<<grid, THREADS>>>(out);
    } else {
        int n = B * U;
        fallback_kernel<<<(n + 255) / 256, 256>>>(x, w, p, bias, out, B, D, U);
    }
}